// round 2
// baseline (speedup 1.0000x reference)
#include <cuda_runtime.h>
#include <math.h>

// ---------------------------------------------------------------------------
// Problem constants
// ---------------------------------------------------------------------------
constexpr int B   = 2;
constexpr int N   = 2048;
constexpr int C   = 1024;
constexpr int H   = 16;
constexpr int D   = 64;       // C / H
constexpr int DFF = 4096;     // 4 * C
constexpr int BN_ROWS = B * N;        // 4096
constexpr float EPS = 1e-5f;
constexpr float SCALE = 0.125f;       // D^-0.5 = 1/8

// ---------------------------------------------------------------------------
// Scratch (device globals; no allocations allowed)
// ---------------------------------------------------------------------------
__device__ float g_xn[BN_ROWS * C];         // ln1(x) / ln2(x1) (reused)
__device__ float g_qkv[BN_ROWS * 3 * C];    // qkv projection
__device__ float g_attnout[BN_ROWS * C];    // attn @ v, heads merged
__device__ float g_x1[BN_ROWS * C];         // x + proj(attnout)
__device__ float g_h[BN_ROWS * DFF];        // gelu(fc1)

// ---------------------------------------------------------------------------
// LayerNorm: one block per row, row cached in shared
// ---------------------------------------------------------------------------
__global__ void ln_kernel(const float* __restrict__ x,
                          const float* __restrict__ g,
                          const float* __restrict__ b,
                          float* __restrict__ out) {
    const int row = blockIdx.x;
    const int tid = threadIdx.x;
    const float* xr = x + (size_t)row * C;

    __shared__ float sdata[C];
    __shared__ float red[256];

    float lsum = 0.f;
    for (int i = tid; i < C; i += 256) {
        float v = xr[i];
        sdata[i] = v;
        lsum += v;
    }
    red[tid] = lsum;
    __syncthreads();
    for (int s = 128; s > 0; s >>= 1) {
        if (tid < s) red[tid] += red[tid + s];
        __syncthreads();
    }
    const float mu = red[0] * (1.0f / C);
    __syncthreads();

    float lvar = 0.f;
    for (int i = tid; i < C; i += 256) {
        float d = sdata[i] - mu;
        lvar += d * d;
    }
    red[tid] = lvar;
    __syncthreads();
    for (int s = 128; s > 0; s >>= 1) {
        if (tid < s) red[tid] += red[tid + s];
        __syncthreads();
    }
    const float rstd = rsqrtf(red[0] * (1.0f / C) + EPS);

    float* outr = out + (size_t)row * C;
    for (int i = tid; i < C; i += 256) {
        outr[i] = (sdata[i] - mu) * rstd * g[i] + b[i];
    }
}

// ---------------------------------------------------------------------------
// Tiled SGEMM: C = alpha * A * op(B) (+ epilogue)
//   A: [M,K] row-major, lda
//   TRANSB=true : B is [Nc,K] row-major (NT, torch Linear weights)
//   TRANSB=false: B is [K,Nc] row-major (NN)
// Batched over blockIdx.z with (b,h) decomposition: off = b*s?b + h*s?h
// EPI: 0 = none, 2 = +bias +resid, 3 = +bias, exact GELU
// Tiles: 64x64x16, 256 threads, 4x4 per thread. All dims divide exactly.
// ---------------------------------------------------------------------------
__device__ __forceinline__ float gelu_exact(float v) {
    return 0.5f * v * (1.0f + erff(v * 0.70710678118654752f));
}

template<bool TRANSB, int EPI>
__global__ void __launch_bounds__(256)
gemm64(const float* __restrict__ A, int lda, long long sAb, long long sAh,
       const float* __restrict__ Bp, int ldb, long long sBb, long long sBh,
       float* __restrict__ Cp, int ldc, long long sCb, long long sCh,
       int K, float alpha, int nH,
       const float* __restrict__ bias,
       const float* __restrict__ resid, int ldres, long long sRb, long long sRh) {
    const int z  = blockIdx.z;
    const int bz = z / nH;
    const int hz = z % nH;
    A  += (size_t)bz * sAb + (size_t)hz * sAh;
    Bp += (size_t)bz * sBb + (size_t)hz * sBh;
    Cp += (size_t)bz * sCb + (size_t)hz * sCh;
    if (EPI == 2) resid += (size_t)bz * sRb + (size_t)hz * sRh;

    __shared__ float As[16][64];
    __shared__ float Bs[16][64];

    const int tid  = threadIdx.x;
    const int tcol = tid & 15;   // 16 col groups
    const int trow = tid >> 4;   // 16 row groups

    const int m0 = blockIdx.y * 64;
    const int n0 = blockIdx.x * 64;

    float acc[4][4] = {};

    for (int k0 = 0; k0 < K; k0 += 16) {
        // load A tile 64x16 -> As[k][m]
        #pragma unroll
        for (int i = tid; i < 1024; i += 256) {
            int r = i >> 4, c = i & 15;
            As[c][r] = A[(size_t)(m0 + r) * lda + (k0 + c)];
        }
        if (TRANSB) {
            #pragma unroll
            for (int i = tid; i < 1024; i += 256) {
                int r = i >> 4, c = i & 15;
                Bs[c][r] = Bp[(size_t)(n0 + r) * ldb + (k0 + c)];
            }
        } else {
            #pragma unroll
            for (int i = tid; i < 1024; i += 256) {
                int r = i >> 6, c = i & 63;
                Bs[r][c] = Bp[(size_t)(k0 + r) * ldb + (n0 + c)];
            }
        }
        __syncthreads();

        #pragma unroll
        for (int k = 0; k < 16; k++) {
            float4 av = *reinterpret_cast<const float4*>(&As[k][trow * 4]);
            float4 bv = *reinterpret_cast<const float4*>(&Bs[k][tcol * 4]);
            float a[4] = {av.x, av.y, av.z, av.w};
            float bq[4] = {bv.x, bv.y, bv.z, bv.w};
            #pragma unroll
            for (int i = 0; i < 4; i++)
                #pragma unroll
                for (int j = 0; j < 4; j++)
                    acc[i][j] += a[i] * bq[j];
        }
        __syncthreads();
    }

    // epilogue
    #pragma unroll
    for (int i = 0; i < 4; i++) {
        const int r = m0 + trow * 4 + i;
        #pragma unroll
        for (int j = 0; j < 4; j++) {
            const int cI = n0 + tcol * 4 + j;
            float v = acc[i][j] * alpha;
            if (EPI == 2) v += bias[cI] + resid[(size_t)r * ldres + cI];
            if (EPI == 3) v = gelu_exact(v + bias[cI]);
            Cp[(size_t)r * ldc + cI] = v;
        }
    }
}

// ---------------------------------------------------------------------------
// Masked in-place softmax over rows of attn [B*H*N, N]
// ---------------------------------------------------------------------------
__global__ void softmax_kernel(float* __restrict__ attn,
                               const int* __restrict__ mask) {
    const long long row = blockIdx.x;           // over B*H*N
    const int b = (int)(row / ((long long)H * N));
    float* p = attn + row * (long long)N;
    const int* mrow = mask + (size_t)b * N;
    const int tid = threadIdx.x;

    __shared__ float red[256];

    float vals[8];  // N / 256 = 8
    float lmax = -INFINITY;
    #pragma unroll
    for (int j = 0; j < 8; j++) {
        int i = tid + j * 256;
        float v = mrow[i] ? p[i] : -INFINITY;
        vals[j] = v;
        lmax = fmaxf(lmax, v);
    }
    red[tid] = lmax;
    __syncthreads();
    for (int s = 128; s > 0; s >>= 1) {
        if (tid < s) red[tid] = fmaxf(red[tid], red[tid + s]);
        __syncthreads();
    }
    const float rowmax = red[0];
    __syncthreads();

    float lsum = 0.f;
    #pragma unroll
    for (int j = 0; j < 8; j++) {
        float e = __expf(vals[j] - rowmax);
        vals[j] = e;
        lsum += e;
    }
    red[tid] = lsum;
    __syncthreads();
    for (int s = 128; s > 0; s >>= 1) {
        if (tid < s) red[tid] += red[tid + s];
        __syncthreads();
    }
    const float inv = 1.0f / red[0];

    #pragma unroll
    for (int j = 0; j < 8; j++) {
        p[tid + j * 256] = vals[j] * inv;
    }
}

// ---------------------------------------------------------------------------
// Host launcher
// ---------------------------------------------------------------------------
extern "C" void kernel_launch(void* const* d_in, const int* in_sizes, int n_in,
                              void* d_out, int out_size) {
    const float* x      = (const float*)d_in[0];
    const int*   mask   = (const int*)  d_in[1];
    const float* qkv_w  = (const float*)d_in[2];
    const float* proj_w = (const float*)d_in[3];
    const float* proj_b = (const float*)d_in[4];
    const float* ln1_g  = (const float*)d_in[5];
    const float* ln1_b  = (const float*)d_in[6];
    const float* ln2_g  = (const float*)d_in[7];
    const float* ln2_b  = (const float*)d_in[8];
    const float* fc1_w  = (const float*)d_in[9];
    const float* fc1_b  = (const float*)d_in[10];
    const float* fc2_w  = (const float*)d_in[11];
    const float* fc2_b  = (const float*)d_in[12];

    float* out_x    = (float*)d_out;
    float* out_attn = out_x + (size_t)B * N * C;

    float *xn, *qkv, *attnout, *x1, *hbuf;
    cudaGetSymbolAddress((void**)&xn,      g_xn);
    cudaGetSymbolAddress((void**)&qkv,     g_qkv);
    cudaGetSymbolAddress((void**)&attnout, g_attnout);
    cudaGetSymbolAddress((void**)&x1,      g_x1);
    cudaGetSymbolAddress((void**)&hbuf,    g_h);

    const long long sQKVb = (long long)N * 3 * C;  // batch stride in qkv buffer
    const long long sAttb = (long long)H * N * N;
    const long long sAtth = (long long)N * N;

    // 1) ln1(x) -> xn
    ln_kernel<<<BN_ROWS, 256>>>(x, ln1_g, ln1_b, xn);

    // 2) qkv = xn @ qkv_w^T   [4096,1024]x[3072,1024]^T -> [4096,3072]
    gemm64<true, 0><<<dim3(3 * C / 64, BN_ROWS / 64, 1), 256>>>(
        xn, C, 0, 0,
        qkv_w, C, 0, 0,
        qkv, 3 * C, 0, 0,
        C, 1.0f, 1, nullptr, nullptr, 0, 0, 0);

    // 3) scores = scale * Q @ K^T  (batched over B*H), written into out_attn
    gemm64<true, 0><<<dim3(N / 64, N / 64, B * H), 256>>>(
        qkv,          3 * C, sQKVb, D,        // Q: off h*D
        qkv + C,      3 * C, sQKVb, D,        // K: off C + h*D
        out_attn,     N,     sAttb, sAtth,
        D, SCALE, H, nullptr, nullptr, 0, 0, 0);

    // 4) masked softmax in place
    softmax_kernel<<<B * H * N, 256>>>(out_attn, mask);

    // 5) attnout = attn @ V (batched, NN), heads merged into [B*N, C]
    gemm64<false, 0><<<dim3(1, N / 64, B * H), 256>>>(
        out_attn,      N,     sAttb, sAtth,
        qkv + 2 * C,   3 * C, sQKVb, D,
        attnout,       C,     (long long)N * C, D,
        N, 1.0f, H, nullptr, nullptr, 0, 0, 0);

    // 6) x1 = x + attnout @ proj_w^T + proj_b
    gemm64<true, 2><<<dim3(C / 64, BN_ROWS / 64, 1), 256>>>(
        attnout, C, 0, 0,
        proj_w,  C, 0, 0,
        x1,      C, 0, 0,
        C, 1.0f, 1, proj_b, x, C, 0, 0);

    // 7) ln2(x1) -> xn (reuse)
    ln_kernel<<<BN_ROWS, 256>>>(x1, ln2_g, ln2_b, xn);

    // 8) h = gelu(xn @ fc1_w^T + fc1_b)
    gemm64<true, 3><<<dim3(DFF / 64, BN_ROWS / 64, 1), 256>>>(
        xn,    C, 0, 0,
        fc1_w, C, 0, 0,
        hbuf,  DFF, 0, 0,
        C, 1.0f, 1, fc1_b, nullptr, 0, 0, 0);

    // 9) out_x = x1 + h @ fc2_w^T + fc2_b
    gemm64<true, 2><<<dim3(C / 64, BN_ROWS / 64, 1), 256>>>(
        hbuf,  DFF, 0, 0,
        fc2_w, DFF, 0, 0,
        out_x, C, 0, 0,
        DFF, 1.0f, 1, fc2_b, x1, C, 0, 0);
}

// round 5
// speedup vs baseline: 3.8056x; 3.8056x over previous
#include <cuda_runtime.h>
#include <cuda_bf16.h>
#include <math.h>
#include <stdint.h>

constexpr int B = 2, N = 2048, C = 1024, H = 16, D = 64, DFF = 4096;
constexpr int BNR = B * N;   // 4096
constexpr float EPS = 1e-5f;

// ---------------- low-level helpers (sm_80+ PTX only: no tcgen05) ----------
__device__ __forceinline__ uint32_t smem_u32(const void* p) {
    uint32_t a;
    asm("{ .reg .u64 t; cvta.to.shared.u64 t, %1; cvt.u32.u64 %0, t; }" : "=r"(a) : "l"(p));
    return a;
}
__device__ __forceinline__ void cpasync16(uint32_t dst, const void* src) {
    asm volatile("cp.async.cg.shared.global [%0], [%1], 16;" :: "r"(dst), "l"(src));
}
__device__ __forceinline__ void cp_commit() {
    asm volatile("cp.async.commit_group;");
}
template<int Nw>
__device__ __forceinline__ void cp_wait() {
    asm volatile("cp.async.wait_group %0;" :: "n"(Nw));
}
__device__ __forceinline__ void ldsm4(uint32_t* r, uint32_t addr) {
    asm volatile("ldmatrix.sync.aligned.m8n8.x4.shared.b16 {%0,%1,%2,%3}, [%4];"
        : "=r"(r[0]), "=r"(r[1]), "=r"(r[2]), "=r"(r[3]) : "r"(addr));
}
__device__ __forceinline__ void mma16816(float* d, const uint32_t* a, const uint32_t* b) {
    asm volatile("mma.sync.aligned.m16n8k16.row.col.f32.bf16.bf16.f32 "
        "{%0,%1,%2,%3}, {%4,%5,%6,%7}, {%8,%9}, {%0,%1,%2,%3};"
        : "+f"(d[0]), "+f"(d[1]), "+f"(d[2]), "+f"(d[3])
        : "r"(a[0]), "r"(a[1]), "r"(a[2]), "r"(a[3]), "r"(b[0]), "r"(b[1]));
}
__device__ __forceinline__ float gelu_exact(float v) {
    return 0.5f * v * (1.0f + erff(v * 0.70710678118654752f));
}
__device__ __forceinline__ void split2store(__nv_bfloat16* hi, __nv_bfloat16* lo,
                                            float v0, float v1) {
    __nv_bfloat16 h0 = __float2bfloat16(v0), h1 = __float2bfloat16(v1);
    __nv_bfloat162 hh(h0, h1);
    __nv_bfloat162 ll(__float2bfloat16(v0 - __bfloat162float(h0)),
                      __float2bfloat16(v1 - __bfloat162float(h1)));
    *reinterpret_cast<__nv_bfloat162*>(hi) = hh;
    *reinterpret_cast<__nv_bfloat162*>(lo) = ll;
}

// ---------------- scratch ----------------
#define GA __device__ __align__(256)
GA __nv_bfloat16 g_xnh[BNR * C],      g_xnl[BNR * C];
GA __nv_bfloat16 g_qwh[3 * C * C],    g_qwl[3 * C * C];
GA __nv_bfloat16 g_pwh[C * C],        g_pwl[C * C];
GA __nv_bfloat16 g_f1h[DFF * C],      g_f1l[DFF * C];
GA __nv_bfloat16 g_f2h[C * DFF],      g_f2l[C * DFF];
GA __nv_bfloat16 g_qh[BNR * 3 * C],   g_ql[BNR * 3 * C];
GA __nv_bfloat16 g_ath[(size_t)B * H * N * N], g_atl[(size_t)B * H * N * N];
GA __nv_bfloat16 g_vth[B * H * D * N], g_vtl[B * H * D * N];
GA __nv_bfloat16 g_aoh[BNR * C],      g_aol[BNR * C];
GA __nv_bfloat16 g_hh[BNR * DFF],     g_hl[BNR * DFF];
GA float g_x1[BNR * C];

// ---------------- fp32 -> (hi,lo) bf16 split ----------------
__global__ void split_kernel(const float* __restrict__ s, __nv_bfloat16* __restrict__ hi,
                             __nv_bfloat16* __restrict__ lo, int n4) {
    int i = blockIdx.x * 256 + threadIdx.x;
    if (i >= n4) return;
    float4 v = reinterpret_cast<const float4*>(s)[i];
    __nv_bfloat16 h0 = __float2bfloat16(v.x), h1 = __float2bfloat16(v.y);
    __nv_bfloat16 h2 = __float2bfloat16(v.z), h3 = __float2bfloat16(v.w);
    __nv_bfloat162 ha(h0, h1), hb(h2, h3);
    __nv_bfloat162 la(__float2bfloat16(v.x - __bfloat162float(h0)), __float2bfloat16(v.y - __bfloat162float(h1)));
    __nv_bfloat162 lb(__float2bfloat16(v.z - __bfloat162float(h2)), __float2bfloat16(v.w - __bfloat162float(h3)));
    reinterpret_cast<uint2*>(hi)[i] = make_uint2(*(uint32_t*)&ha, *(uint32_t*)&hb);
    reinterpret_cast<uint2*>(lo)[i] = make_uint2(*(uint32_t*)&la, *(uint32_t*)&lb);
}

// ---------------- LayerNorm -> split ----------------
__global__ void ln_split(const float* __restrict__ x, const float* __restrict__ g,
                         const float* __restrict__ b, __nv_bfloat16* __restrict__ hi,
                         __nv_bfloat16* __restrict__ lo) {
    const int row = blockIdx.x, tid = threadIdx.x;
    const float* xr = x + (size_t)row * C;
    __shared__ float sd[C];
    __shared__ float red[256];
    float ls = 0.f;
    for (int i = tid; i < C; i += 256) { float v = xr[i]; sd[i] = v; ls += v; }
    red[tid] = ls; __syncthreads();
    for (int s = 128; s > 0; s >>= 1) { if (tid < s) red[tid] += red[tid + s]; __syncthreads(); }
    const float mu = red[0] * (1.0f / C); __syncthreads();
    float lv = 0.f;
    for (int i = tid; i < C; i += 256) { float d = sd[i] - mu; lv += d * d; }
    red[tid] = lv; __syncthreads();
    for (int s = 128; s > 0; s >>= 1) { if (tid < s) red[tid] += red[tid + s]; __syncthreads(); }
    const float rstd = rsqrtf(red[0] * (1.0f / C) + EPS);
    for (int i = tid; i < C; i += 256) {
        float v = (sd[i] - mu) * rstd * g[i] + b[i];
        __nv_bfloat16 h = __float2bfloat16(v);
        hi[(size_t)row * C + i] = h;
        lo[(size_t)row * C + i] = __float2bfloat16(v - __bfloat162float(h));
    }
}

// ---------------- masked softmax (in-place fp32) + hi/lo emit ----------------
__global__ void softmax_kernel(float* __restrict__ attn, const int* __restrict__ mask,
                               __nv_bfloat16* __restrict__ hi, __nv_bfloat16* __restrict__ lo) {
    const long long row = blockIdx.x;
    const int b = (int)(row / ((long long)H * N));
    float* p = attn + row * (long long)N;
    const int* mr = mask + (size_t)b * N;
    const int tid = threadIdx.x;
    __shared__ float red[256];
    float vals[8];
    float lmax = -INFINITY;
    #pragma unroll
    for (int j = 0; j < 8; j++) {
        int i = tid + j * 256;
        float v = mr[i] ? p[i] : -INFINITY;
        vals[j] = v; lmax = fmaxf(lmax, v);
    }
    red[tid] = lmax; __syncthreads();
    for (int s = 128; s > 0; s >>= 1) { if (tid < s) red[tid] = fmaxf(red[tid], red[tid + s]); __syncthreads(); }
    const float rm = red[0]; __syncthreads();
    float ls = 0.f;
    #pragma unroll
    for (int j = 0; j < 8; j++) { float e = __expf(vals[j] - rm); vals[j] = e; ls += e; }
    red[tid] = ls; __syncthreads();
    for (int s = 128; s > 0; s >>= 1) { if (tid < s) red[tid] += red[tid + s]; __syncthreads(); }
    const float inv = 1.0f / red[0];
    #pragma unroll
    for (int j = 0; j < 8; j++) {
        long long i = row * (long long)N + tid + j * 256;
        float v = vals[j] * inv;
        p[tid + j * 256] = v;
        __nv_bfloat16 h = __float2bfloat16(v);
        hi[i] = h;
        lo[i] = __float2bfloat16(v - __bfloat162float(h));
    }
}

// ---------------- V transpose: qkv[.,2C+h*64+d] -> vt[b,h,d,n] ----------------
__global__ void vtrans(const __nv_bfloat16* __restrict__ qh, const __nv_bfloat16* __restrict__ ql,
                       __nv_bfloat16* __restrict__ vh, __nv_bfloat16* __restrict__ vl) {
    const int z = blockIdx.z, b = z >> 4, h = z & 15;
    const int n0 = blockIdx.x * 32, tid = threadIdx.x;
    __shared__ __nv_bfloat16 sh[64][33], sl[64][33];
    for (int i = tid; i < 2048; i += 256) {
        int r = i >> 6, d = i & 63;
        size_t o = (size_t)(b * N + n0 + r) * (3 * C) + 2 * C + h * 64 + d;
        sh[d][r] = qh[o]; sl[d][r] = ql[o];
    }
    __syncthreads();
    for (int i = tid; i < 2048; i += 256) {
        int d = i >> 5, c = i & 31;
        size_t o = (size_t)z * D * N + (size_t)d * N + n0 + c;
        vh[o] = sh[d][c]; vl[o] = sl[d][c];
    }
}

// ===========================================================================
// HMMA GEMM (NT): C[M,Nc] = A[M,K] * B[Nc,K]^T with bf16 hi/lo x3 products.
// CTA tile 128 x BN_, BK=32, 8 warps (warp tile 32 x BN_/2), cp.async double
// buffer. SMEM rows padded to 80B -> conflict-free ldmatrix.
// EPI: 0 = *0.125 -> fp32   1 = split -> hi/lo   2 = +bias+resid -> fp32
//      3 = gelu(+bias) -> split hi/lo
// ===========================================================================
template<int BN_, int EPI>
__global__ void __launch_bounds__(256, 1) hgemm(
    const __nv_bfloat16* __restrict__ Ah, const __nv_bfloat16* __restrict__ Al,
    int lda, long long sAb, long long sAh,
    const __nv_bfloat16* __restrict__ Bh, const __nv_bfloat16* __restrict__ Bl,
    int ldb, long long sBb, long long sBh,
    float* __restrict__ Cf, __nv_bfloat16* __restrict__ Chi, __nv_bfloat16* __restrict__ Clo,
    int ldc, long long sCb, long long sCh,
    int K, const float* __restrict__ bias, const float* __restrict__ resid) {
    extern __shared__ char smem[];
    constexpr int ROWB = 80;                       // padded row bytes (32 bf16 + pad)
    constexpr int ATILE = 128 * ROWB;              // 10240
    constexpr int STAGE = 2 * ATILE + 2 * BN_ * ROWB;
    constexpr int WTN = BN_ / 2;                   // warp n-tile
    constexpr int NA = WTN / 8;                    // n atoms per warp

    const int tid = threadIdx.x, lane = tid & 31, wid = tid >> 5;
    const int wm = wid & 3, wn = wid >> 2;
    const int z = blockIdx.z, bz = z >> 4, hz = z & 15;
    Ah += (size_t)bz * sAb + (size_t)hz * sAh;
    Al += (size_t)bz * sAb + (size_t)hz * sAh;
    Bh += (size_t)bz * sBb + (size_t)hz * sBh;
    Bl += (size_t)bz * sBb + (size_t)hz * sBh;
    const size_t coff = (size_t)bz * sCb + (size_t)hz * sCh;
    const int m0 = blockIdx.y * 128, n0 = blockIdx.x * BN_;
    const uint32_t sbase = smem_u32(smem);

    auto load_stage = [&](int s, int k0) {
        const uint32_t st = sbase + s * STAGE;
        #pragma unroll
        for (int i = tid; i < 512; i += 256) {
            int r = i >> 2, c4 = i & 3;
            uint32_t d = st + r * ROWB + c4 * 16;
            cpasync16(d,         Ah + (size_t)(m0 + r) * lda + k0 + c4 * 8);
            cpasync16(d + ATILE, Al + (size_t)(m0 + r) * lda + k0 + c4 * 8);
        }
        #pragma unroll
        for (int i = tid; i < BN_ * 4; i += 256) {
            int r = i >> 2, c4 = i & 3;
            uint32_t d = st + 2 * ATILE + r * ROWB + c4 * 16;
            cpasync16(d,              Bh + (size_t)(n0 + r) * ldb + k0 + c4 * 8);
            cpasync16(d + BN_ * ROWB, Bl + (size_t)(n0 + r) * ldb + k0 + c4 * 8);
        }
        cp_commit();
    };

    float acc[2][NA][4];
    #pragma unroll
    for (int a = 0; a < 2; a++)
        #pragma unroll
        for (int b2 = 0; b2 < NA; b2++)
            #pragma unroll
            for (int c = 0; c < 4; c++) acc[a][b2][c] = 0.f;

    const int nch = K >> 5;
    load_stage(0, 0);
    for (int ch = 0; ch < nch; ch++) {
        if (ch + 1 < nch) { load_stage((ch + 1) & 1, (ch + 1) << 5); cp_wait<1>(); }
        else cp_wait<0>();
        __syncthreads();

        const uint32_t st  = sbase + (ch & 1) * STAGE;
        const uint32_t bst = st + 2 * ATILE;
        const int arow = wm * 32 + (lane & 15);
        const int acolb = ((lane >> 4) << 4);       // (lane>=16 ? 8 elems : 0) * 2B
        const int brow = (lane & 7) + ((lane >> 4) << 3);
        const int bcolb = (((lane >> 3) & 1) << 4);
        #pragma unroll
        for (int ks = 0; ks < 2; ks++) {
            uint32_t afh[2][4], afl[2][4];
            #pragma unroll
            for (int ma = 0; ma < 2; ma++) {
                uint32_t ad = st + (arow + ma * 16) * ROWB + ks * 32 + acolb;
                ldsm4(afh[ma], ad);
                ldsm4(afl[ma], ad + ATILE);
            }
            uint32_t bfh[NA][2], bfl[NA][2];
            #pragma unroll
            for (int p = 0; p < NA / 2; p++) {
                uint32_t r4[4];
                uint32_t bd = bst + (wn * WTN + p * 16 + brow) * ROWB + ks * 32 + bcolb;
                ldsm4(r4, bd);
                bfh[2*p][0] = r4[0]; bfh[2*p][1] = r4[1];
                bfh[2*p+1][0] = r4[2]; bfh[2*p+1][1] = r4[3];
                ldsm4(r4, bd + BN_ * ROWB);
                bfl[2*p][0] = r4[0]; bfl[2*p][1] = r4[1];
                bfl[2*p+1][0] = r4[2]; bfl[2*p+1][1] = r4[3];
            }
            #pragma unroll
            for (int ma = 0; ma < 2; ma++)
                #pragma unroll
                for (int na = 0; na < NA; na++) {
                    mma16816(acc[ma][na], afh[ma], bfh[na]);
                    mma16816(acc[ma][na], afh[ma], bfl[na]);
                    mma16816(acc[ma][na], afl[ma], bfh[na]);
                }
        }
        __syncthreads();
    }

    // epilogue: direct stores (thread owns (row, 2-col) pairs)
    #pragma unroll
    for (int ma = 0; ma < 2; ma++)
        #pragma unroll
        for (int na = 0; na < NA; na++) {
            const int gr0 = m0 + wm * 32 + ma * 16 + (lane >> 2);
            const int gc  = n0 + wn * WTN + na * 8 + ((lane & 3) << 1);
            #pragma unroll
            for (int h2 = 0; h2 < 2; h2++) {
                const int gr = gr0 + h2 * 8;
                float v0 = acc[ma][na][h2 * 2], v1 = acc[ma][na][h2 * 2 + 1];
                const size_t o = coff + (size_t)gr * ldc + gc;
                if (EPI == 0) {
                    float2 t = make_float2(v0 * 0.125f, v1 * 0.125f);
                    *reinterpret_cast<float2*>(Cf + o) = t;
                }
                if (EPI == 1) split2store(Chi + o, Clo + o, v0, v1);
                if (EPI == 2) {
                    float2 t = make_float2(
                        v0 + bias[gc]     + resid[(size_t)gr * ldc + gc],
                        v1 + bias[gc + 1] + resid[(size_t)gr * ldc + gc + 1]);
                    *reinterpret_cast<float2*>(Cf + o) = t;
                }
                if (EPI == 3) {
                    float t0 = gelu_exact(v0 + bias[gc]);
                    float t1 = gelu_exact(v1 + bias[gc + 1]);
                    split2store(Chi + o, Clo + o, t0, t1);
                }
            }
        }
}

constexpr int SMB128 = 2 * (2 * 128 * 80 + 2 * 128 * 80);  // 81920
constexpr int SMB64  = 2 * (2 * 128 * 80 + 2 * 64 * 80);   // 61440

// ---------------- host ----------------
extern "C" void kernel_launch(void* const* d_in, const int* in_sizes, int n_in,
                              void* d_out, int out_size) {
    const float* x      = (const float*)d_in[0];
    const int*   mask   = (const int*)  d_in[1];
    const float* qkv_w  = (const float*)d_in[2];
    const float* proj_w = (const float*)d_in[3];
    const float* proj_b = (const float*)d_in[4];
    const float* ln1_g  = (const float*)d_in[5];
    const float* ln1_b  = (const float*)d_in[6];
    const float* ln2_g  = (const float*)d_in[7];
    const float* ln2_b  = (const float*)d_in[8];
    const float* fc1_w  = (const float*)d_in[9];
    const float* fc1_b  = (const float*)d_in[10];
    const float* fc2_w  = (const float*)d_in[11];
    const float* fc2_b  = (const float*)d_in[12];
    float* out_x    = (float*)d_out;
    float* out_attn = out_x + (size_t)B * N * C;

    cudaFuncSetAttribute(hgemm<128,0>, cudaFuncAttributeMaxDynamicSharedMemorySize, SMB128);
    cudaFuncSetAttribute(hgemm<128,1>, cudaFuncAttributeMaxDynamicSharedMemorySize, SMB128);
    cudaFuncSetAttribute(hgemm<128,2>, cudaFuncAttributeMaxDynamicSharedMemorySize, SMB128);
    cudaFuncSetAttribute(hgemm<128,3>, cudaFuncAttributeMaxDynamicSharedMemorySize, SMB128);
    cudaFuncSetAttribute(hgemm<64,1>,  cudaFuncAttributeMaxDynamicSharedMemorySize, SMB64);

    __nv_bfloat16 *xnh, *xnl, *qwh, *qwl, *pwh, *pwl, *f1h, *f1l, *f2h, *f2l;
    __nv_bfloat16 *qh, *ql, *ath, *atl, *vth, *vtl, *aoh, *aol, *hh, *hl;
    float* x1;
    cudaGetSymbolAddress((void**)&xnh, g_xnh); cudaGetSymbolAddress((void**)&xnl, g_xnl);
    cudaGetSymbolAddress((void**)&qwh, g_qwh); cudaGetSymbolAddress((void**)&qwl, g_qwl);
    cudaGetSymbolAddress((void**)&pwh, g_pwh); cudaGetSymbolAddress((void**)&pwl, g_pwl);
    cudaGetSymbolAddress((void**)&f1h, g_f1h); cudaGetSymbolAddress((void**)&f1l, g_f1l);
    cudaGetSymbolAddress((void**)&f2h, g_f2h); cudaGetSymbolAddress((void**)&f2l, g_f2l);
    cudaGetSymbolAddress((void**)&qh,  g_qh);  cudaGetSymbolAddress((void**)&ql,  g_ql);
    cudaGetSymbolAddress((void**)&ath, g_ath); cudaGetSymbolAddress((void**)&atl, g_atl);
    cudaGetSymbolAddress((void**)&vth, g_vth); cudaGetSymbolAddress((void**)&vtl, g_vtl);
    cudaGetSymbolAddress((void**)&aoh, g_aoh); cudaGetSymbolAddress((void**)&aol, g_aol);
    cudaGetSymbolAddress((void**)&hh,  g_hh);  cudaGetSymbolAddress((void**)&hl,  g_hl);
    cudaGetSymbolAddress((void**)&x1,  g_x1);

    // weight splits
    split_kernel<<<3 * C * C / 4 / 256, 256>>>(qkv_w, qwh, qwl, 3 * C * C / 4);
    split_kernel<<<C * C / 4 / 256, 256>>>(proj_w, pwh, pwl, C * C / 4);
    split_kernel<<<DFF * C / 4 / 256, 256>>>(fc1_w, f1h, f1l, DFF * C / 4);
    split_kernel<<<C * DFF / 4 / 256, 256>>>(fc2_w, f2h, f2l, C * DFF / 4);

    // 1) ln1 -> xn (hi/lo)
    ln_split<<<BNR, 256>>>(x, ln1_g, ln1_b, xnh, xnl);
    // 2) qkv = xn @ qkv_w^T -> split
    hgemm<128,1><<<dim3(24, 32, 1), 256, SMB128>>>(
        xnh, xnl, C, 0, 0, qwh, qwl, C, 0, 0,
        nullptr, qh, ql, 3 * C, 0, 0, C, nullptr, nullptr);
    // 3) scores = 0.125 * Q @ K^T -> out_attn fp32 (batched over B*H)
    hgemm<128,0><<<dim3(16, 16, 32), 256, SMB128>>>(
        qh, ql, 3 * C, (long long)N * 3 * C, 64,
        qh + C, ql + C, 3 * C, (long long)N * 3 * C, 64,
        out_attn, nullptr, nullptr, N, (long long)H * N * N, (long long)N * N,
        64, nullptr, nullptr);
    // 4) masked softmax (+ hi/lo emit)
    softmax_kernel<<<B * H * N, 256>>>(out_attn, mask, ath, atl);
    // 5) V transpose (per-head [D, N] hi/lo)
    vtrans<<<dim3(N / 32, 1, B * H), 256>>>(qh, ql, vth, vtl);
    // 6) ao = attn @ V^T_t -> split (heads merged [B*N, C])
    hgemm<64,1><<<dim3(1, 16, 32), 256, SMB64>>>(
        ath, atl, N, (long long)H * N * N, (long long)N * N,
        vth, vtl, N, (long long)H * D * N, (long long)D * N,
        nullptr, aoh, aol, C, (long long)N * C, 64,
        N, nullptr, nullptr);
    // 7) x1 = x + ao @ proj_w^T + proj_b
    hgemm<128,2><<<dim3(8, 32, 1), 256, SMB128>>>(
        aoh, aol, C, 0, 0, pwh, pwl, C, 0, 0,
        x1, nullptr, nullptr, C, 0, 0, C, proj_b, x);
    // 8) ln2 -> xn (hi/lo)
    ln_split<<<BNR, 256>>>(x1, ln2_g, ln2_b, xnh, xnl);
    // 9) h = gelu(xn @ fc1_w^T + fc1_b) -> split
    hgemm<128,3><<<dim3(32, 32, 1), 256, SMB128>>>(
        xnh, xnl, C, 0, 0, f1h, f1l, C, 0, 0,
        nullptr, hh, hl, DFF, 0, 0, C, fc1_b, nullptr);
    // 10) out_x = x1 + h @ fc2_w^T + fc2_b
    hgemm<128,2><<<dim3(8, 32, 1), 256, SMB128>>>(
        hh, hl, DFF, 0, 0, f2h, f2l, DFF, 0, 0,
        out_x, nullptr, nullptr, C, 0, 0, DFF, fc2_b, x1);
}